// round 6
// baseline (speedup 1.0000x reference)
#include <cuda_runtime.h>

// Problem dims
#define IN_   26
#define H1_   64
#define H2_   32
#define F1_   16
#define OUT_  10
#define T_    1000
#define B_    512
#define NB    4              // batch elements per block
#define NTHREADS 256
#define NBLOCKS (B_ / NB)    // 128

typedef unsigned long long u64;

// Shared memory layout (16B-aligned members first).
struct Smem {
    float4 xs[2][IN_];        // double-buffered x_t, [buf][i] -> 4 batch lanes
    float4 h1[H1_];           // LSTM1 hidden, [j] -> 4 batch lanes
    float4 c1[H1_];
    float4 h2[H2_];
    float4 c2[H2_];
    float4 act1[4 * H1_];     // activated LSTM1 gates (i,f,g,o blocks of 64)
    float4 act2[4 * H2_];     // activated LSTM2 gates (i,f,g,o blocks of 32)
    u64    wih1p[IN_ * 4 * H1_];  // [i][g] splatted {w,w} pairs (53 KB)
    float  wih2f[H1_ * 4 * H2_];  // [j][g] scalar (32 KB) - unsplatted, less crossbar
    float  whh2f[H2_ * 4 * H2_];  // [k][g] scalar (16 KB)
    float  wfc1[F1_ * H2_];
    float  bfc1[F1_];
    float  wfc2[OUT_ * F1_];
    float  bfc2[OUT_];
    float  fc1s[NB][F1_];
};

// ---- packed f32x2 helpers (sm_100+ PTX) ----
__device__ __forceinline__ void ffma2(u64& acc, u64 a, u64 b) {
    asm("fma.rn.f32x2 %0, %1, %2, %0;" : "+l"(acc) : "l"(a), "l"(b));
}
__device__ __forceinline__ u64 splat2(float w) {
    u64 r;
    asm("mov.b64 %0, {%1, %1};" : "=l"(r) : "r"(__float_as_uint(w)));
    return r;
}
__device__ __forceinline__ float2 unpack2(u64 v) {
    float2 r;
    asm("mov.b64 {%0, %1}, %2;" : "=f"(r.x), "=f"(r.y) : "l"(v));
    return r;
}

// Saturating fast activations (NaN-free at extremes: exp->inf, rcp(inf)=0).
__device__ __forceinline__ float sigm(float v) {
    return __fdividef(1.0f, 1.0f + __expf(-v));
}
__device__ __forceinline__ float tanh_f(float v) {
    return 1.0f - __fdividef(2.0f, 1.0f + __expf(2.0f * v));
}

__global__ __launch_bounds__(NTHREADS, 1)
void audio_lstm_kernel(const float* __restrict__ x,
                       const float* __restrict__ w_ih1, const float* __restrict__ w_hh1,
                       const float* __restrict__ b_ih1, const float* __restrict__ b_hh1,
                       const float* __restrict__ w_ih2, const float* __restrict__ w_hh2,
                       const float* __restrict__ b_ih2, const float* __restrict__ b_hh2,
                       const float* __restrict__ w_fc1, const float* __restrict__ b_fc1,
                       const float* __restrict__ w_fc2, const float* __restrict__ b_fc2,
                       float* __restrict__ out)
{
    extern __shared__ unsigned char smem_raw[];
    Smem& s = *reinterpret_cast<Smem*>(smem_raw);

    const int tid = threadIdx.x;
    const int blk = blockIdx.x;

    // ---- Preamble: stage weights ----
    for (int e = tid; e < IN_ * 256; e += NTHREADS) {
        int i = e >> 8, g = e & 255;
        s.wih1p[e] = splat2(w_ih1[g * IN_ + i]);   // splatted: all 8 warps read it
    }
    for (int e = tid; e < H1_ * 128; e += NTHREADS) {
        int j = e >> 7, g = e & 127;
        s.wih2f[e] = w_ih2[g * H1_ + j];           // scalar: halves crossbar traffic
    }
    for (int e = tid; e < H2_ * 128; e += NTHREADS) {
        int k = e >> 7, g = e & 127;
        s.whh2f[e] = w_hh2[g * H2_ + k];
    }
    for (int e = tid; e < F1_ * H2_; e += NTHREADS) s.wfc1[e] = w_fc1[e];
    if (tid < F1_)  s.bfc1[tid] = b_fc1[tid];
    for (int e = tid; e < OUT_ * F1_; e += NTHREADS) s.wfc2[e] = w_fc2[e];
    if (tid < OUT_) s.bfc2[tid] = b_fc2[tid];

    // Zero states
    if (tid < H1_) {
        s.h1[tid] = make_float4(0.f, 0.f, 0.f, 0.f);
        s.c1[tid] = make_float4(0.f, 0.f, 0.f, 0.f);
    }
    if (tid < H2_) {
        s.h2[tid] = make_float4(0.f, 0.f, 0.f, 0.f);
        s.c2[tid] = make_float4(0.f, 0.f, 0.f, 0.f);
    }

    // LSTM1 recurrent weights: register-resident pre-splatted {w,w} pairs.
    // 64 u64 = 128 regs/thread -> ~160 live regs total, no spill risk.
    const int g1 = tid;              // 0..255
    const int type1 = tid >> 6;      // 0:i 1:f 2:g 3:o (warp-uniform)
    u64 whr[H1_];
    #pragma unroll
    for (int j = 0; j < H1_; j++) whr[j] = splat2(w_hh1[g1 * H1_ + j]);
    const u64 b1p = splat2(b_ih1[g1] + b_hh1[g1]);

    const int type2 = (tid >> 5) & 3;
    const u64 b2p = (tid < 128) ? splat2(b_ih2[tid] + b_hh2[tid]) : 0ull;

    // x mapping: x[b,0,i,t] at b*IN*T + i*T + t.
    // Loaders in warps 4-7 (LSTM1-only warps with issue slack).
    const int lidx = tid - 128;          // 0..103 for loaders
    const bool is_loader = (lidx >= 0) && (lidx < NB * IN_);
    const int xi = is_loader ? (lidx % IN_) : 0;
    const int xb = is_loader ? (lidx / IN_) : 0;
    const float* xptr = x + (size_t)(blk * NB + xb) * IN_ * T_ + (size_t)xi * T_;
    if (is_loader) {
        reinterpret_cast<float*>(s.xs[0])[xi * 4 + xb] = xptr[0];
    }
    __syncthreads();

    // ---- Pipelined main loop ----
    // Iteration k: Phase A computes LSTM1 gates(k) and LSTM2 gates(k-1)
    //              (both read h1(k-1)); Phase B runs both state updates.
    int buf = 0;
    #pragma unroll 1
    for (int k = 0; k <= T_; k++) {
        const bool do1 = (k < T_);
        const bool do2 = (k > 0);

        // Prefetch next x (L2-resident after first replay; hidden under Phase A)
        float xpre = 0.f;
        const bool pre = do1 && is_loader && (k + 1 < T_);
        if (pre) xpre = xptr[k + 1];

        // ---- Phase A: LSTM1 gates (all 256 threads) ----
        if (do1) {
            u64 a01 = b1p, a23 = b1p;
            const ulonglong2* xsb = reinterpret_cast<const ulonglong2*>(s.xs[buf]);
            #pragma unroll
            for (int i = 0; i < IN_; i++) {
                u64 w2 = s.wih1p[i * 256 + g1];  // LDS.64, conflict-free
                ulonglong2 xv = xsb[i];          // broadcast LDS.128
                ffma2(a01, w2, xv.x);
                ffma2(a23, w2, xv.y);
            }
            const ulonglong2* h1b = reinterpret_cast<const ulonglong2*>(s.h1);
            #pragma unroll
            for (int j = 0; j < H1_; j++) {
                ulonglong2 hv = h1b[j];          // broadcast LDS.128
                ffma2(a01, whr[j], hv.x);
                ffma2(a23, whr[j], hv.y);
            }
            float2 p0 = unpack2(a01), p1 = unpack2(a23);
            float4 a;
            if (type1 == 2) {
                a.x = tanh_f(p0.x); a.y = tanh_f(p0.y);
                a.z = tanh_f(p1.x); a.w = tanh_f(p1.y);
            } else {
                a.x = sigm(p0.x); a.y = sigm(p0.y);
                a.z = sigm(p1.x); a.w = sigm(p1.y);
            }
            s.act1[g1] = a;
        }

        // ---- Phase A: LSTM2 gates for step k-1 (threads 0..127) ----
        if (do2 && tid < 128) {
            u64 a01 = b2p, a23 = b2p;
            const ulonglong2* h1b = reinterpret_cast<const ulonglong2*>(s.h1);
            #pragma unroll
            for (int j = 0; j < H1_; j++) {
                u64 w2 = splat2(s.wih2f[j * 128 + tid]); // LDS.32 + reg splat
                ulonglong2 hv = h1b[j];                  // broadcast
                ffma2(a01, w2, hv.x);
                ffma2(a23, w2, hv.y);
            }
            const ulonglong2* h2b = reinterpret_cast<const ulonglong2*>(s.h2);
            #pragma unroll
            for (int kk = 0; kk < H2_; kk++) {
                u64 w2 = splat2(s.whh2f[kk * 128 + tid]);
                ulonglong2 hv = h2b[kk];
                ffma2(a01, w2, hv.x);
                ffma2(a23, w2, hv.y);
            }
            float2 p0 = unpack2(a01), p1 = unpack2(a23);
            float4 a;
            if (type2 == 2) {
                a.x = tanh_f(p0.x); a.y = tanh_f(p0.y);
                a.z = tanh_f(p1.x); a.w = tanh_f(p1.y);
            } else {
                a.x = sigm(p0.x); a.y = sigm(p0.y);
                a.z = sigm(p1.x); a.w = sigm(p1.y);
            }
            s.act2[tid] = a;
        }

        if (pre) reinterpret_cast<float*>(s.xs[buf ^ 1])[xi * 4 + xb] = xpre;
        __syncthreads();

        // ---- Phase B: state updates on warps 4-6 (slack warps) ----
        if (do1 && tid >= 128 && tid < 128 + H1_) {   // warps 4-5: LSTM1 -> h1(k)
            int u = tid - 128;
            float4 iv = s.act1[u];
            float4 fv = s.act1[H1_ + u];
            float4 gv = s.act1[2 * H1_ + u];
            float4 ov = s.act1[3 * H1_ + u];
            float4 c  = s.c1[u];
            c.x = fmaf(fv.x, c.x, iv.x * gv.x);
            c.y = fmaf(fv.y, c.y, iv.y * gv.y);
            c.z = fmaf(fv.z, c.z, iv.z * gv.z);
            c.w = fmaf(fv.w, c.w, iv.w * gv.w);
            float4 h;
            h.x = ov.x * tanh_f(c.x); h.y = ov.y * tanh_f(c.y);
            h.z = ov.z * tanh_f(c.z); h.w = ov.w * tanh_f(c.w);
            s.c1[u] = c;
            s.h1[u] = h;
        }
        if (do2 && tid >= 192 && tid < 192 + H2_) {   // warp 6: LSTM2 -> h2(k-1)
            int u = tid - 192;
            float4 iv = s.act2[u];
            float4 fv = s.act2[H2_ + u];
            float4 gv = s.act2[2 * H2_ + u];
            float4 ov = s.act2[3 * H2_ + u];
            float4 c  = s.c2[u];
            c.x = fmaf(fv.x, c.x, iv.x * gv.x);
            c.y = fmaf(fv.y, c.y, iv.y * gv.y);
            c.z = fmaf(fv.z, c.z, iv.z * gv.z);
            c.w = fmaf(fv.w, c.w, iv.w * gv.w);
            float4 h;
            h.x = ov.x * tanh_f(c.x); h.y = ov.y * tanh_f(c.y);
            h.z = ov.z * tanh_f(c.z); h.w = ov.w * tanh_f(c.w);
            s.c2[u] = c;
            s.h2[u] = h;
        }
        __syncthreads();

        buf ^= 1;
    }

    // ---- FC head on final h2 = h2(T-1) ----
    if (tid < NB * F1_) {
        int b = tid >> 4, f = tid & 15;
        float acc = s.bfc1[f];
        #pragma unroll
        for (int k = 0; k < H2_; k++)
            acc = fmaf(reinterpret_cast<float*>(&s.h2[k])[b], s.wfc1[f * H2_ + k], acc);
        s.fc1s[b][f] = fmaxf(acc, 0.f);
    }
    __syncthreads();
    if (tid < NB * OUT_) {
        int b = tid / OUT_, o = tid % OUT_;
        float acc = s.bfc2[o];
        #pragma unroll
        for (int f = 0; f < F1_; f++)
            acc = fmaf(s.fc1s[b][f], s.wfc2[o * F1_ + f], acc);
        out[(blk * NB + b) * OUT_ + o] = acc;
    }
}

extern "C" void kernel_launch(void* const* d_in, const int* in_sizes, int n_in,
                              void* d_out, int out_size)
{
    const float* x     = (const float*)d_in[0];
    const float* w_ih1 = (const float*)d_in[1];
    const float* w_hh1 = (const float*)d_in[2];
    const float* b_ih1 = (const float*)d_in[3];
    const float* b_hh1 = (const float*)d_in[4];
    const float* w_ih2 = (const float*)d_in[5];
    const float* w_hh2 = (const float*)d_in[6];
    const float* b_ih2 = (const float*)d_in[7];
    const float* b_hh2 = (const float*)d_in[8];
    const float* w_fc1 = (const float*)d_in[9];
    const float* b_fc1 = (const float*)d_in[10];
    const float* w_fc2 = (const float*)d_in[11];
    const float* b_fc2 = (const float*)d_in[12];
    float* out = (float*)d_out;

    static_assert(sizeof(Smem) < 220 * 1024, "smem too big");
    cudaFuncSetAttribute(audio_lstm_kernel,
                         cudaFuncAttributeMaxDynamicSharedMemorySize,
                         (int)sizeof(Smem));

    audio_lstm_kernel<<<NBLOCKS, NTHREADS, sizeof(Smem)>>>(
        x, w_ih1, w_hh1, b_ih1, b_hh1,
        w_ih2, w_hh2, b_ih2, b_hh2,
        w_fc1, b_fc1, w_fc2, b_fc2, out);
}